// round 1
// baseline (speedup 1.0000x reference)
#include <cuda_runtime.h>

#define NPIX (512*512)
#define FEATS 32

__global__ __launch_bounds__(256) void g_tensor3d_kernel(
    const float* __restrict__ z,        // [8]
    const float* __restrict__ data,     // [512,512,32]
    const float* __restrict__ z_data,   // [64,32]
    const float* __restrict__ lerp,     // [NPIX,2]  (wx, wy)
    const int*   __restrict__ x0,
    const int*   __restrict__ y0,
    const int*   __restrict__ x1,
    const int*   __restrict__ y1,
    const float* __restrict__ W1,       // [32,32] row-major (i, j)
    const float* __restrict__ b1,       // [32]
    const float* __restrict__ W2,       // [32,32]
    const float* __restrict__ b2,       // [32]
    const float* __restrict__ W3,       // [32,1]
    const float* __restrict__ b3,       // [1]
    float*       __restrict__ out)      // [8, NPIX]
{
    __shared__ float sW1[1024];
    __shared__ float sW2[1024];
    __shared__ float sW3[32];
    __shared__ float sb1[32];
    __shared__ float sb2[32];
    __shared__ float szf[8][32];
    __shared__ float sb3v;

    const int tid = threadIdx.x;

    // Stage weights into shared (broadcast-read later).
    #pragma unroll
    for (int i = tid; i < 1024; i += 256) {
        sW1[i] = W1[i];
        sW2[i] = W2[i];
    }
    if (tid < 32) {
        sW3[tid] = W3[tid];
        sb1[tid] = b1[tid];
        sb2[tid] = b2[tid];
    }
    if (tid == 0) sb3v = b3[0];

    // Per-batch z feature: zf[b][i] = lerp(z_data[z0i], z_data[z1i], zl)
    {
        const int b = tid >> 5;
        const int i = tid & 31;
        const float zn = 63.0f * z[b];           // (Z_DIM-1)*(z-0)/(1-0)
        const float zt = truncf(zn);
        int z0i = (int)zn;
        if (z0i < 0) z0i = 0;
        if (z0i > 63) z0i = 63;
        int z1i = z0i + 1;
        if (z1i > 63) z1i = 63;
        const float zl = zn - zt;
        szf[b][i] = z_data[z0i * 32 + i] * (1.0f - zl) + z_data[z1i * 32 + i] * zl;
    }
    __syncthreads();

    const int p = blockIdx.x * 256 + tid;

    const float wx = lerp[2 * p + 0];
    const float wy = lerp[2 * p + 1];
    const int ix0 = x0[p], iy0 = y0[p], ix1 = x1[p], iy1 = y1[p];

    const float4* p00 = (const float4*)(data + (iy0 * 512 + ix0) * 32);
    const float4* p10 = (const float4*)(data + (iy0 * 512 + ix1) * 32);
    const float4* p01 = (const float4*)(data + (iy1 * 512 + ix0) * 32);
    const float4* p11 = (const float4*)(data + (iy1 * 512 + ix1) * 32);

    const float w00 = (1.0f - wx) * (1.0f - wy);
    const float w10 = wx * (1.0f - wy);
    const float w01 = (1.0f - wx) * wy;
    const float w11 = wx * wy;

    // Bilinear gather -> per-pixel feature vector (batch-invariant).
    float xy[32];
    #pragma unroll
    for (int q = 0; q < 8; q++) {
        const float4 a = p00[q];
        const float4 c = p10[q];
        const float4 e = p01[q];
        const float4 g = p11[q];
        xy[4 * q + 0] = a.x * w00 + c.x * w10 + e.x * w01 + g.x * w11;
        xy[4 * q + 1] = a.y * w00 + c.y * w10 + e.y * w01 + g.y * w11;
        xy[4 * q + 2] = a.z * w00 + c.z * w10 + e.z * w01 + g.z * w11;
        xy[4 * q + 3] = a.w * w00 + c.w * w10 + e.w * w01 + g.w * w11;
    }

    // MLP per batch. Batch loop rolled (code size), inner GEMVs fully unrolled.
    #pragma unroll 1
    for (int b = 0; b < 8; b++) {
        float h1[32];
        #pragma unroll
        for (int j = 0; j < 32; j++) h1[j] = sb1[j];

        #pragma unroll
        for (int i = 0; i < 32; i++) {
            const float f = xy[i] * szf[b][i];
            #pragma unroll
            for (int j = 0; j < 32; j++)
                h1[j] = fmaf(f, sW1[i * 32 + j], h1[j]);
        }

        float h2[32];
        #pragma unroll
        for (int j = 0; j < 32; j++) h2[j] = sb2[j];

        #pragma unroll
        for (int i = 0; i < 32; i++) {
            const float f = fmaxf(h1[i], 0.0f);   // relu fused into operand
            #pragma unroll
            for (int j = 0; j < 32; j++)
                h2[j] = fmaf(f, sW2[i * 32 + j], h2[j]);
        }

        float o = sb3v;
        #pragma unroll
        for (int i = 0; i < 32; i++)
            o = fmaf(fmaxf(h2[i], 0.0f), sW3[i], o);

        out[b * NPIX + p] = o;
    }
}

extern "C" void kernel_launch(void* const* d_in, const int* in_sizes, int n_in,
                              void* d_out, int out_size) {
    const float* z      = (const float*)d_in[0];
    const float* data   = (const float*)d_in[1];
    const float* z_data = (const float*)d_in[2];
    const float* lerp   = (const float*)d_in[3];
    const int*   x0     = (const int*)d_in[4];
    const int*   y0     = (const int*)d_in[5];
    const int*   x1     = (const int*)d_in[6];
    const int*   y1     = (const int*)d_in[7];
    const float* W1     = (const float*)d_in[8];
    const float* b1     = (const float*)d_in[9];
    const float* W2     = (const float*)d_in[10];
    const float* b2     = (const float*)d_in[11];
    const float* W3     = (const float*)d_in[12];
    const float* b3     = (const float*)d_in[13];
    float* out = (float*)d_out;

    g_tensor3d_kernel<<<NPIX / 256, 256>>>(z, data, z_data, lerp,
                                           x0, y0, x1, y1,
                                           W1, b1, W2, b2, W3, b3, out);
}

// round 3
// speedup vs baseline: 1.3090x; 1.3090x over previous
#include <cuda_runtime.h>
#include <cstdint>

#define NPIX (512*512)

typedef unsigned long long u64;

// Packed fp32x2 FMA (Blackwell-only; not emitted by ptxas from C++).
__device__ __forceinline__ u64 ffma2(u64 a, u64 b, u64 c) {
    u64 d;
    asm("fma.rn.f32x2 %0, %1, %2, %3;" : "=l"(d) : "l"(a), "l"(b), "l"(c));
    return d;
}
__device__ __forceinline__ u64 dup2(float f) {
    u64 d;
    unsigned r = __float_as_uint(f);
    asm("mov.b64 %0, {%1, %1};" : "=l"(d) : "r"(r));
    return d;
}
__device__ __forceinline__ u64 pack2(float lo, float hi) {
    u64 d;
    asm("mov.b64 %0, {%1, %2};" : "=l"(d) : "r"(__float_as_uint(lo)), "r"(__float_as_uint(hi)));
    return d;
}
__device__ __forceinline__ float2 unpack2(u64 v) {
    float2 r;
    unsigned lo, hi;
    asm("mov.b64 {%0, %1}, %2;" : "=r"(lo), "=r"(hi) : "l"(v));
    r.x = __uint_as_float(lo); r.y = __uint_as_float(hi);
    return r;
}

// NOTE: no minBlocksPerMultiprocessor — let ptxas use up to 255 regs so the
// 96-reg live set (xy + h1 + h2, all packed) never spills (spills trip the
// harness's device-memory guard).
__global__ __launch_bounds__(256) void g_tensor3d_kernel(
    const float* __restrict__ z,        // [8]
    const float* __restrict__ data,     // [512,512,32]
    const float* __restrict__ z_data,   // [64,32]
    const float* __restrict__ lerp,     // [NPIX,2]
    const int*   __restrict__ x0,
    const int*   __restrict__ y0,
    const int*   __restrict__ x1,
    const int*   __restrict__ y1,
    const float* __restrict__ W1,       // [32,32]
    const float* __restrict__ b1,
    const float* __restrict__ W2,       // [32,32]
    const float* __restrict__ b2,
    const float* __restrict__ W3,       // [32]
    const float* __restrict__ b3,
    float*       __restrict__ out)      // [8, NPIX]
{
    // Weights packed as f32x2 pairs over the j (output) dimension.
    __shared__ ulonglong2 sW1p[256];    // row i: 8 ulonglong2 = 16 j-pairs
    __shared__ ulonglong2 sW2p[256];
    __shared__ u64 sW3p[16];
    __shared__ u64 sb1p[16];
    __shared__ u64 sb2p[16];
    __shared__ float szf[8][32];
    __shared__ float sb3v;

    const int tid = threadIdx.x;

    sW1p[tid] = ((const ulonglong2*)W1)[tid];
    sW2p[tid] = ((const ulonglong2*)W2)[tid];
    if (tid < 16) {
        sW3p[tid] = ((const u64*)W3)[tid];
        sb1p[tid] = ((const u64*)b1)[tid];
        sb2p[tid] = ((const u64*)b2)[tid];
    }
    if (tid == 0) sb3v = b3[0];

    // Per-batch z features.
    {
        const int b = tid >> 5;
        const int i = tid & 31;
        const float zn = 63.0f * z[b];
        const float zt = truncf(zn);
        int z0i = (int)zn;
        if (z0i < 0) z0i = 0;
        if (z0i > 63) z0i = 63;
        int z1i = z0i + 1;
        if (z1i > 63) z1i = 63;
        const float zl = zn - zt;
        szf[b][i] = z_data[z0i * 32 + i] * (1.0f - zl) + z_data[z1i * 32 + i] * zl;
    }
    __syncthreads();

    const int p = blockIdx.x * 256 + tid;

    const float wx = lerp[2 * p + 0];
    const float wy = lerp[2 * p + 1];
    const int ix0 = x0[p], iy0 = y0[p], ix1 = x1[p], iy1 = y1[p];

    const float4* p00 = (const float4*)(data + (iy0 * 512 + ix0) * 32);
    const float4* p10 = (const float4*)(data + (iy0 * 512 + ix1) * 32);
    const float4* p01 = (const float4*)(data + (iy1 * 512 + ix0) * 32);
    const float4* p11 = (const float4*)(data + (iy1 * 512 + ix1) * 32);

    const float w00 = (1.0f - wx) * (1.0f - wy);
    const float w10 = wx * (1.0f - wy);
    const float w01 = (1.0f - wx) * wy;
    const float w11 = wx * wy;

    // Bilinear gather -> batch-invariant pixel feature (registers).
    float xy[32];
    #pragma unroll
    for (int q = 0; q < 8; q++) {
        const float4 a = p00[q];
        const float4 c = p10[q];
        const float4 e = p01[q];
        const float4 g = p11[q];
        xy[4 * q + 0] = a.x * w00 + c.x * w10 + e.x * w01 + g.x * w11;
        xy[4 * q + 1] = a.y * w00 + c.y * w10 + e.y * w01 + g.y * w11;
        xy[4 * q + 2] = a.z * w00 + c.z * w10 + e.z * w01 + g.z * w11;
        xy[4 * q + 3] = a.w * w00 + c.w * w10 + e.w * w01 + g.w * w11;
    }

    float* outp = out + p;

    #pragma unroll 1
    for (int b = 0; b < 8; b++) {
        const float* zf = szf[b];

        // ---- Layer 1: h1 = (xy .* zf) @ W1 + b1, packed over j ----
        u64 h1[16];
        #pragma unroll
        for (int jp = 0; jp < 16; jp++) h1[jp] = sb1p[jp];

        #pragma unroll
        for (int i = 0; i < 32; i++) {
            const u64 fd = dup2(xy[i] * zf[i]);
            const ulonglong2* w = &sW1p[i * 8];
            #pragma unroll
            for (int q = 0; q < 8; q++) {
                const ulonglong2 wv = w[q];
                h1[2 * q + 0] = ffma2(fd, wv.x, h1[2 * q + 0]);
                h1[2 * q + 1] = ffma2(fd, wv.y, h1[2 * q + 1]);
            }
        }

        // ---- Layer 2: consume h1 pairwise (ReLU applied on the fly; no a1[]) ----
        u64 h2[16];
        #pragma unroll
        for (int jp = 0; jp < 16; jp++) h2[jp] = sb2p[jp];

        #pragma unroll
        for (int ip = 0; ip < 16; ip++) {
            const float2 v = unpack2(h1[ip]);
            const u64 f0 = dup2(fmaxf(v.x, 0.0f));   // activation i = 2*ip
            const u64 f1 = dup2(fmaxf(v.y, 0.0f));   // activation i = 2*ip+1
            const ulonglong2* w0 = &sW2p[(2 * ip) * 8];
            #pragma unroll
            for (int q = 0; q < 8; q++) {
                const ulonglong2 wv = w0[q];
                h2[2 * q + 0] = ffma2(f0, wv.x, h2[2 * q + 0]);
                h2[2 * q + 1] = ffma2(f0, wv.y, h2[2 * q + 1]);
            }
            const ulonglong2* w1 = &sW2p[(2 * ip + 1) * 8];
            #pragma unroll
            for (int q = 0; q < 8; q++) {
                const ulonglong2 wv = w1[q];
                h2[2 * q + 0] = ffma2(f1, wv.x, h2[2 * q + 0]);
                h2[2 * q + 1] = ffma2(f1, wv.y, h2[2 * q + 1]);
            }
        }

        // ---- Layer 3: scalar dot with relu(h2) ----
        u64 acc = pack2(sb3v, 0.0f);
        #pragma unroll
        for (int jp = 0; jp < 16; jp++) {
            const float2 v = unpack2(h2[jp]);
            const u64 rv = pack2(fmaxf(v.x, 0.0f), fmaxf(v.y, 0.0f));
            acc = ffma2(rv, sW3p[jp], acc);
        }
        const float2 af = unpack2(acc);
        outp[b * NPIX] = af.x + af.y;
    }
}

extern "C" void kernel_launch(void* const* d_in, const int* in_sizes, int n_in,
                              void* d_out, int out_size) {
    const float* z      = (const float*)d_in[0];
    const float* data   = (const float*)d_in[1];
    const float* z_data = (const float*)d_in[2];
    const float* lerp   = (const float*)d_in[3];
    const int*   x0     = (const int*)d_in[4];
    const int*   y0     = (const int*)d_in[5];
    const int*   x1     = (const int*)d_in[6];
    const int*   y1     = (const int*)d_in[7];
    const float* W1     = (const float*)d_in[8];
    const float* b1     = (const float*)d_in[9];
    const float* W2     = (const float*)d_in[10];
    const float* b2     = (const float*)d_in[11];
    const float* W3     = (const float*)d_in[12];
    const float* b3     = (const float*)d_in[13];
    float* out = (float*)d_out;

    g_tensor3d_kernel<<<NPIX / 256, 256>>>(z, data, z_data, lerp,
                                           x0, y0, x1, y1,
                                           W1, b1, W2, b2, W3, b3, out);
}

// round 4
// speedup vs baseline: 15.3301x; 11.7117x over previous
#include <cuda_runtime.h>
#include <cstdint>

#define NPIX (512*512)

typedef unsigned long long u64;

// Packed fp32x2 FMA (Blackwell-only; not emitted by ptxas from C++).
__device__ __forceinline__ u64 ffma2(u64 a, u64 b, u64 c) {
    u64 d;
    asm("fma.rn.f32x2 %0, %1, %2, %3;" : "=l"(d) : "l"(a), "l"(b), "l"(c));
    return d;
}
__device__ __forceinline__ u64 dup2(float f) {
    u64 d;
    unsigned r = __float_as_uint(f);
    asm("mov.b64 %0, {%1, %1};" : "=l"(d) : "r"(r));
    return d;
}
__device__ __forceinline__ u64 pack2(float lo, float hi) {
    u64 d;
    asm("mov.b64 %0, {%1, %2};" : "=l"(d) : "r"(__float_as_uint(lo)), "r"(__float_as_uint(hi)));
    return d;
}
__device__ __forceinline__ float2 unpack2(u64 v) {
    float2 r;
    unsigned lo, hi;
    asm("mov.b64 {%0, %1}, %2;" : "=r"(lo), "=r"(hi) : "l"(v));
    r.x = __uint_as_float(lo); r.y = __uint_as_float(hi);
    return r;
}

// Anti-hoist shared loads: volatile asm cannot be CSE'd or moved out of the
// batch loop, so weights are re-read (broadcast LDS, conflict-free) each
// iteration instead of being promoted to ~1000 registers (the R0/R3 spill).
__device__ __forceinline__ uint32_t sptr(const void* p) {
    return (uint32_t)__cvta_generic_to_shared(p);
}
__device__ __forceinline__ ulonglong2 lds128v(uint32_t addr) {
    ulonglong2 v;
    asm volatile("ld.shared.v2.u64 {%0, %1}, [%2];" : "=l"(v.x), "=l"(v.y) : "r"(addr));
    return v;
}
__device__ __forceinline__ u64 lds64v(uint32_t addr) {
    u64 v;
    asm volatile("ld.shared.u64 %0, [%1];" : "=l"(v) : "r"(addr));
    return v;
}

__global__ __launch_bounds__(128) void g_tensor3d_kernel(
    const float* __restrict__ z,        // [8]
    const float* __restrict__ data,     // [512,512,32]
    const float* __restrict__ z_data,   // [64,32]
    const float* __restrict__ lerp,     // [NPIX,2]
    const int*   __restrict__ x0,
    const int*   __restrict__ y0,
    const int*   __restrict__ x1,
    const int*   __restrict__ y1,
    const float* __restrict__ W1,       // [32,32]
    const float* __restrict__ b1,
    const float* __restrict__ W2,       // [32,32]
    const float* __restrict__ b2,
    const float* __restrict__ W3,       // [32]
    const float* __restrict__ b3,
    float*       __restrict__ out)      // [8, NPIX]
{
    // Weights packed as f32x2 pairs over the j (output) dimension.
    __shared__ ulonglong2 sW1p[256];    // row i: 8 ulonglong2 = 16 j-pairs
    __shared__ ulonglong2 sW2p[256];
    __shared__ u64 sW3p[16];
    __shared__ u64 sb1p[16];
    __shared__ u64 sb2p[16];
    __shared__ float szf[8][32];
    __shared__ float sb3v;

    const int tid = threadIdx.x;

    #pragma unroll
    for (int k = 0; k < 2; k++) {
        sW1p[tid + 128 * k] = ((const ulonglong2*)W1)[tid + 128 * k];
        sW2p[tid + 128 * k] = ((const ulonglong2*)W2)[tid + 128 * k];
    }
    if (tid < 16) {
        sW3p[tid] = ((const u64*)W3)[tid];
        sb1p[tid] = ((const u64*)b1)[tid];
        sb2p[tid] = ((const u64*)b2)[tid];
    }
    if (tid == 0) sb3v = b3[0];

    // Per-batch z features (threads 0..255 would cover 8x32; with 128 do 2 rounds).
    #pragma unroll
    for (int k = 0; k < 2; k++) {
        const int t = tid + 128 * k;
        const int b = t >> 5;
        const int i = t & 31;
        const float zn = 63.0f * z[b];
        const float zt = truncf(zn);
        int z0i = (int)zn;
        if (z0i < 0) z0i = 0;
        if (z0i > 63) z0i = 63;
        int z1i = z0i + 1;
        if (z1i > 63) z1i = 63;
        const float zl = zn - zt;
        szf[b][i] = z_data[z0i * 32 + i] * (1.0f - zl) + z_data[z1i * 32 + i] * zl;
    }
    __syncthreads();

    const uint32_t w1base = sptr(sW1p);
    const uint32_t w2base = sptr(sW2p);
    const uint32_t w3base = sptr(sW3p);
    const uint32_t b1base = sptr(sb1p);
    const uint32_t b2base = sptr(sb2p);

    const int p = blockIdx.x * 128 + tid;

    const float wx = lerp[2 * p + 0];
    const float wy = lerp[2 * p + 1];
    const int ix0 = x0[p], iy0 = y0[p], ix1 = x1[p], iy1 = y1[p];

    const float4* p00 = (const float4*)(data + (iy0 * 512 + ix0) * 32);
    const float4* p10 = (const float4*)(data + (iy0 * 512 + ix1) * 32);
    const float4* p01 = (const float4*)(data + (iy1 * 512 + ix0) * 32);
    const float4* p11 = (const float4*)(data + (iy1 * 512 + ix1) * 32);

    const float w00 = (1.0f - wx) * (1.0f - wy);
    const float w10 = wx * (1.0f - wy);
    const float w01 = (1.0f - wx) * wy;
    const float w11 = wx * wy;

    // Bilinear gather -> batch-invariant pixel feature (registers).
    float xy[32];
    #pragma unroll
    for (int q = 0; q < 8; q++) {
        const float4 a = p00[q];
        const float4 c = p10[q];
        const float4 e = p01[q];
        const float4 g = p11[q];
        xy[4 * q + 0] = a.x * w00 + c.x * w10 + e.x * w01 + g.x * w11;
        xy[4 * q + 1] = a.y * w00 + c.y * w10 + e.y * w01 + g.y * w11;
        xy[4 * q + 2] = a.z * w00 + c.z * w10 + e.z * w01 + g.z * w11;
        xy[4 * q + 3] = a.w * w00 + c.w * w10 + e.w * w01 + g.w * w11;
    }

    float* outp = out + p;

    #pragma unroll 1
    for (int b = 0; b < 8; b++) {
        const float* zf = szf[b];

        // ---- Layer 1: h1 = (xy .* zf) @ W1 + b1, packed over j ----
        u64 h1[16];
        #pragma unroll
        for (int jp = 0; jp < 16; jp++) h1[jp] = lds64v(b1base + 8 * jp);

        #pragma unroll
        for (int i = 0; i < 32; i++) {
            const u64 fd = dup2(xy[i] * zf[i]);
            #pragma unroll
            for (int q = 0; q < 8; q++) {
                const ulonglong2 wv = lds128v(w1base + (i * 8 + q) * 16);
                h1[2 * q + 0] = ffma2(fd, wv.x, h1[2 * q + 0]);
                h1[2 * q + 1] = ffma2(fd, wv.y, h1[2 * q + 1]);
            }
        }

        // ---- Layer 2: consume h1 pairwise (ReLU on the fly, in place) ----
        u64 h2[16];
        #pragma unroll
        for (int jp = 0; jp < 16; jp++) h2[jp] = lds64v(b2base + 8 * jp);

        #pragma unroll
        for (int ip = 0; ip < 16; ip++) {
            const float2 v = unpack2(h1[ip]);
            const u64 f0 = dup2(fmaxf(v.x, 0.0f));
            const u64 f1 = dup2(fmaxf(v.y, 0.0f));
            #pragma unroll
            for (int q = 0; q < 8; q++) {
                const ulonglong2 wv = lds128v(w2base + ((2 * ip) * 8 + q) * 16);
                h2[2 * q + 0] = ffma2(f0, wv.x, h2[2 * q + 0]);
                h2[2 * q + 1] = ffma2(f0, wv.y, h2[2 * q + 1]);
            }
            #pragma unroll
            for (int q = 0; q < 8; q++) {
                const ulonglong2 wv = lds128v(w2base + ((2 * ip + 1) * 8 + q) * 16);
                h2[2 * q + 0] = ffma2(f1, wv.x, h2[2 * q + 0]);
                h2[2 * q + 1] = ffma2(f1, wv.y, h2[2 * q + 1]);
            }
        }

        // ---- Layer 3: scalar dot with relu(h2) ----
        u64 acc = pack2(sb3v, 0.0f);
        #pragma unroll
        for (int jp = 0; jp < 16; jp++) {
            const float2 v = unpack2(h2[jp]);
            const u64 rv = pack2(fmaxf(v.x, 0.0f), fmaxf(v.y, 0.0f));
            acc = ffma2(rv, lds64v(w3base + 8 * jp), acc);
        }
        const float2 af = unpack2(acc);
        outp[b * NPIX] = af.x + af.y;
    }
}

extern "C" void kernel_launch(void* const* d_in, const int* in_sizes, int n_in,
                              void* d_out, int out_size) {
    const float* z      = (const float*)d_in[0];
    const float* data   = (const float*)d_in[1];
    const float* z_data = (const float*)d_in[2];
    const float* lerp   = (const float*)d_in[3];
    const int*   x0     = (const int*)d_in[4];
    const int*   y0     = (const int*)d_in[5];
    const int*   x1     = (const int*)d_in[6];
    const int*   y1     = (const int*)d_in[7];
    const float* W1     = (const float*)d_in[8];
    const float* b1     = (const float*)d_in[9];
    const float* W2     = (const float*)d_in[10];
    const float* b2     = (const float*)d_in[11];
    const float* W3     = (const float*)d_in[12];
    const float* b3     = (const float*)d_in[13];
    float* out = (float*)d_out;

    g_tensor3d_kernel<<<NPIX / 128, 128>>>(z, data, z_data, lerp,
                                           x0, y0, x1, y1,
                                           W1, b1, W2, b2, W3, b3, out);
}

// round 5
// speedup vs baseline: 22.1898x; 1.4475x over previous
#include <cuda_runtime.h>
#include <cstdint>

#define NPIX (512*512)

typedef unsigned long long u64;

// Packed fp32x2 FMA (Blackwell-only; not emitted by ptxas from C++).
__device__ __forceinline__ u64 ffma2(u64 a, u64 b, u64 c) {
    u64 d;
    asm("fma.rn.f32x2 %0, %1, %2, %3;" : "=l"(d) : "l"(a), "l"(b), "l"(c));
    return d;
}
__device__ __forceinline__ u64 dup2(float f) {
    u64 d;
    unsigned r = __float_as_uint(f);
    asm("mov.b64 %0, {%1, %1};" : "=l"(d) : "r"(r));
    return d;
}
__device__ __forceinline__ u64 pack2(float lo, float hi) {
    u64 d;
    asm("mov.b64 %0, {%1, %2};" : "=l"(d) : "r"(__float_as_uint(lo)), "r"(__float_as_uint(hi)));
    return d;
}
__device__ __forceinline__ float2 unpack2(u64 v) {
    float2 r;
    unsigned lo, hi;
    asm("mov.b64 {%0, %1}, %2;" : "=r"(lo), "=r"(hi) : "l"(v));
    r.x = __uint_as_float(lo); r.y = __uint_as_float(hi);
    return r;
}

// Anti-hoist shared loads: volatile asm cannot be CSE'd or moved out of the
// batch loop (prevents the 1000-reg weight promotion that spilled in R0/R3).
__device__ __forceinline__ uint32_t sptr(const void* p) {
    return (uint32_t)__cvta_generic_to_shared(p);
}
__device__ __forceinline__ ulonglong2 lds128v(uint32_t addr) {
    ulonglong2 v;
    asm volatile("ld.shared.v2.u64 {%0, %1}, [%2];" : "=l"(v.x), "=l"(v.y) : "r"(addr));
    return v;
}
__device__ __forceinline__ u64 lds64v(uint32_t addr) {
    u64 v;
    asm volatile("ld.shared.u64 %0, [%1];" : "=l"(v) : "r"(addr));
    return v;
}

__global__ __launch_bounds__(128) void g_tensor3d_kernel(
    const float* __restrict__ z,        // [8]
    const float* __restrict__ data,     // [512,512,32]
    const float* __restrict__ z_data,   // [64,32]
    const float* __restrict__ lerp,     // [NPIX,2]
    const int*   __restrict__ x0,
    const int*   __restrict__ y0,
    const int*   __restrict__ x1,
    const int*   __restrict__ y1,
    const float* __restrict__ W1,       // [32,32]
    const float* __restrict__ b1,
    const float* __restrict__ W2,       // [32,32]
    const float* __restrict__ b2,
    const float* __restrict__ W3,       // [32]
    const float* __restrict__ b3,
    float*       __restrict__ out)      // [8, NPIX]
{
    __shared__ ulonglong2 sW1p[256];    // row i: 8 ulonglong2 = 16 j-pairs
    __shared__ ulonglong2 sW2p[256];
    __shared__ u64 sW3p[16];
    __shared__ u64 sb1p[16];
    __shared__ u64 sb2p[16];
    __shared__ float szf[8][32];
    __shared__ float sb3v;

    const int tid = threadIdx.x;

    #pragma unroll
    for (int k = 0; k < 2; k++) {
        sW1p[tid + 128 * k] = ((const ulonglong2*)W1)[tid + 128 * k];
        sW2p[tid + 128 * k] = ((const ulonglong2*)W2)[tid + 128 * k];
    }
    if (tid < 16) {
        sW3p[tid] = ((const u64*)W3)[tid];
        sb1p[tid] = ((const u64*)b1)[tid];
        sb2p[tid] = ((const u64*)b2)[tid];
    }
    if (tid == 0) sb3v = b3[0];

    #pragma unroll
    for (int k = 0; k < 2; k++) {
        const int t = tid + 128 * k;
        const int b = t >> 5;
        const int i = t & 31;
        const float zn = 63.0f * z[b];
        const float zt = truncf(zn);
        int z0i = (int)zn;
        if (z0i < 0) z0i = 0;
        if (z0i > 63) z0i = 63;
        int z1i = z0i + 1;
        if (z1i > 63) z1i = 63;
        const float zl = zn - zt;
        szf[b][i] = z_data[z0i * 32 + i] * (1.0f - zl) + z_data[z1i * 32 + i] * zl;
    }
    __syncthreads();

    const uint32_t w1base = sptr(sW1p);
    const uint32_t w2base = sptr(sW2p);
    const uint32_t w3base = sptr(sW3p);
    const uint32_t b1base = sptr(sb1p);
    const uint32_t b2base = sptr(sb2p);

    const int p = blockIdx.x * 128 + tid;

    const float wx = lerp[2 * p + 0];
    const float wy = lerp[2 * p + 1];
    const int ix0 = x0[p], iy0 = y0[p], ix1 = x1[p], iy1 = y1[p];

    const float4* p00 = (const float4*)(data + (iy0 * 512 + ix0) * 32);
    const float4* p10 = (const float4*)(data + (iy0 * 512 + ix1) * 32);
    const float4* p01 = (const float4*)(data + (iy1 * 512 + ix0) * 32);
    const float4* p11 = (const float4*)(data + (iy1 * 512 + ix1) * 32);

    const float w00 = (1.0f - wx) * (1.0f - wy);
    const float w10 = wx * (1.0f - wy);
    const float w01 = (1.0f - wx) * wy;
    const float w11 = wx * wy;

    float xy[32];
    #pragma unroll
    for (int q = 0; q < 8; q++) {
        const float4 a = p00[q];
        const float4 c = p10[q];
        const float4 e = p01[q];
        const float4 g = p11[q];
        xy[4 * q + 0] = a.x * w00 + c.x * w10 + e.x * w01 + g.x * w11;
        xy[4 * q + 1] = a.y * w00 + c.y * w10 + e.y * w01 + g.y * w11;
        xy[4 * q + 2] = a.z * w00 + c.z * w10 + e.z * w01 + g.z * w11;
        xy[4 * q + 3] = a.w * w00 + c.w * w10 + e.w * w01 + g.w * w11;
    }

    float* outp = out + p;

    // Two batches per pass: each LDS.128 weight read feeds 4 FFMA2
    // (2 batches x 2 j-pairs) -> half the shared traffic of R4.
    #pragma unroll 1
    for (int bp = 0; bp < 4; bp++) {
        const float* zfa = szf[2 * bp + 0];
        const float* zfb = szf[2 * bp + 1];

        // ---- Layer 1 ----
        u64 h1a[16], h1b[16];
        #pragma unroll
        for (int jp = 0; jp < 16; jp++) {
            const u64 bb = lds64v(b1base + 8 * jp);
            h1a[jp] = bb;
            h1b[jp] = bb;
        }

        #pragma unroll
        for (int i = 0; i < 32; i++) {
            const float x = xy[i];
            const u64 fa = dup2(x * zfa[i]);
            const u64 fb = dup2(x * zfb[i]);
            #pragma unroll
            for (int q = 0; q < 8; q++) {
                const ulonglong2 wv = lds128v(w1base + (i * 8 + q) * 16);
                h1a[2 * q + 0] = ffma2(fa, wv.x, h1a[2 * q + 0]);
                h1a[2 * q + 1] = ffma2(fa, wv.y, h1a[2 * q + 1]);
                h1b[2 * q + 0] = ffma2(fb, wv.x, h1b[2 * q + 0]);
                h1b[2 * q + 1] = ffma2(fb, wv.y, h1b[2 * q + 1]);
            }
        }

        // ---- Layer 2 (ReLU on the fly; h1 consumed in place) ----
        u64 h2a[16], h2b[16];
        #pragma unroll
        for (int jp = 0; jp < 16; jp++) {
            const u64 bb = lds64v(b2base + 8 * jp);
            h2a[jp] = bb;
            h2b[jp] = bb;
        }

        #pragma unroll
        for (int ip = 0; ip < 16; ip++) {
            const float2 va = unpack2(h1a[ip]);
            const float2 vb = unpack2(h1b[ip]);
            const u64 f0a = dup2(fmaxf(va.x, 0.0f));
            const u64 f0b = dup2(fmaxf(vb.x, 0.0f));
            #pragma unroll
            for (int q = 0; q < 8; q++) {
                const ulonglong2 wv = lds128v(w2base + ((2 * ip) * 8 + q) * 16);
                h2a[2 * q + 0] = ffma2(f0a, wv.x, h2a[2 * q + 0]);
                h2a[2 * q + 1] = ffma2(f0a, wv.y, h2a[2 * q + 1]);
                h2b[2 * q + 0] = ffma2(f0b, wv.x, h2b[2 * q + 0]);
                h2b[2 * q + 1] = ffma2(f0b, wv.y, h2b[2 * q + 1]);
            }
            const u64 f1a = dup2(fmaxf(va.y, 0.0f));
            const u64 f1b = dup2(fmaxf(vb.y, 0.0f));
            #pragma unroll
            for (int q = 0; q < 8; q++) {
                const ulonglong2 wv = lds128v(w2base + ((2 * ip + 1) * 8 + q) * 16);
                h2a[2 * q + 0] = ffma2(f1a, wv.x, h2a[2 * q + 0]);
                h2a[2 * q + 1] = ffma2(f1a, wv.y, h2a[2 * q + 1]);
                h2b[2 * q + 0] = ffma2(f1b, wv.x, h2b[2 * q + 0]);
                h2b[2 * q + 1] = ffma2(f1b, wv.y, h2b[2 * q + 1]);
            }
        }

        // ---- Layer 3 ----
        u64 acca = pack2(sb3v, 0.0f);
        u64 accb = acca;
        #pragma unroll
        for (int jp = 0; jp < 16; jp++) {
            const u64 w = lds64v(w3base + 8 * jp);
            const float2 va = unpack2(h2a[jp]);
            const float2 vb = unpack2(h2b[jp]);
            acca = ffma2(pack2(fmaxf(va.x, 0.0f), fmaxf(va.y, 0.0f)), w, acca);
            accb = ffma2(pack2(fmaxf(vb.x, 0.0f), fmaxf(vb.y, 0.0f)), w, accb);
        }
        const float2 ra = unpack2(acca);
        const float2 rb = unpack2(accb);
        outp[(2 * bp + 0) * NPIX] = ra.x + ra.y;
        outp[(2 * bp + 1) * NPIX] = rb.x + rb.y;
    }
}

extern "C" void kernel_launch(void* const* d_in, const int* in_sizes, int n_in,
                              void* d_out, int out_size) {
    const float* z      = (const float*)d_in[0];
    const float* data   = (const float*)d_in[1];
    const float* z_data = (const float*)d_in[2];
    const float* lerp   = (const float*)d_in[3];
    const int*   x0     = (const int*)d_in[4];
    const int*   y0     = (const int*)d_in[5];
    const int*   x1     = (const int*)d_in[6];
    const int*   y1     = (const int*)d_in[7];
    const float* W1     = (const float*)d_in[8];
    const float* b1     = (const float*)d_in[9];
    const float* W2     = (const float*)d_in[10];
    const float* b2     = (const float*)d_in[11];
    const float* W3     = (const float*)d_in[12];
    const float* b3     = (const float*)d_in[13];
    float* out = (float*)d_out;

    g_tensor3d_kernel<<<NPIX / 128, 128>>>(z, data, z_data, lerp,
                                           x0, y0, x1, y1,
                                           W1, b1, W2, b2, W3, b3, out);
}

// round 6
// speedup vs baseline: 22.2162x; 1.0012x over previous
#include <cuda_runtime.h>
#include <cstdint>

#define NPIX (512*512)

typedef unsigned long long u64;

// Packed fp32x2 FMA (Blackwell-only; not emitted by ptxas from C++).
__device__ __forceinline__ u64 ffma2(u64 a, u64 b, u64 c) {
    u64 d;
    asm("fma.rn.f32x2 %0, %1, %2, %3;" : "=l"(d) : "l"(a), "l"(b), "l"(c));
    return d;
}
__device__ __forceinline__ u64 dup2(float f) {
    u64 d;
    unsigned r = __float_as_uint(f);
    asm("mov.b64 %0, {%1, %1};" : "=l"(d) : "r"(r));
    return d;
}
__device__ __forceinline__ u64 pack2(float lo, float hi) {
    u64 d;
    asm("mov.b64 %0, {%1, %2};" : "=l"(d) : "r"(__float_as_uint(lo)), "r"(__float_as_uint(hi)));
    return d;
}
__device__ __forceinline__ float2 unpack2(u64 v) {
    float2 r;
    unsigned lo, hi;
    asm("mov.b64 {%0, %1}, %2;" : "=r"(lo), "=r"(hi) : "l"(v));
    r.x = __uint_as_float(lo); r.y = __uint_as_float(hi);
    return r;
}

// Anti-hoist shared accesses: volatile asm cannot be CSE'd or moved across
// the pass loop (prevents the giant weight->register promotion that spilled
// in R0/R2/R3). Volatile asms are ordered among themselves, so the sxy
// store->load pairs are safe too.
__device__ __forceinline__ uint32_t sptr(const void* p) {
    return (uint32_t)__cvta_generic_to_shared(p);
}
__device__ __forceinline__ ulonglong2 lds128v(uint32_t addr) {
    ulonglong2 v;
    asm volatile("ld.shared.v2.u64 {%0, %1}, [%2];" : "=l"(v.x), "=l"(v.y) : "r"(addr));
    return v;
}
__device__ __forceinline__ u64 lds64v(uint32_t addr) {
    u64 v;
    asm volatile("ld.shared.u64 %0, [%1];" : "=l"(v) : "r"(addr));
    return v;
}
__device__ __forceinline__ float4 ldsf4v(uint32_t addr) {
    float4 v;
    asm volatile("ld.shared.v4.f32 {%0, %1, %2, %3}, [%4];"
                 : "=f"(v.x), "=f"(v.y), "=f"(v.z), "=f"(v.w) : "r"(addr));
    return v;
}
__device__ __forceinline__ float ldsf1v(uint32_t addr) {
    float v;
    asm volatile("ld.shared.f32 %0, [%1];" : "=f"(v) : "r"(addr));
    return v;
}
__device__ __forceinline__ void stsf1v(uint32_t addr, float v) {
    asm volatile("st.shared.f32 [%0], %1;" :: "r"(addr), "f"(v));
}

__global__ __launch_bounds__(128) void g_tensor3d_kernel(
    const float* __restrict__ z,        // [8]
    const float* __restrict__ data,     // [512,512,32]
    const float* __restrict__ z_data,   // [64,32]
    const float* __restrict__ lerp,     // [NPIX,2]
    const int*   __restrict__ x0,
    const int*   __restrict__ y0,
    const int*   __restrict__ x1,
    const int*   __restrict__ y1,
    const float* __restrict__ W1,       // [32,32]
    const float* __restrict__ b1,
    const float* __restrict__ W2,       // [32,32]
    const float* __restrict__ b2,
    const float* __restrict__ W3,       // [32]
    const float* __restrict__ b3,
    float*       __restrict__ out)      // [8, NPIX]
{
    __shared__ ulonglong2 sW1p[256];    // row i: 8 ulonglong2 = 16 j-pairs
    __shared__ ulonglong2 sW2p[256];
    __shared__ u64 sW3p[16];
    __shared__ u64 sb1p[16];
    __shared__ u64 sb2p[16];
    __shared__ float szfT[256];         // transposed: [i][b] = szfT[i*8+b]
    __shared__ float sxy[128 * 33];     // per-thread pixel feature, stride 33 (bank-safe)
    __shared__ float sb3v;

    const int tid = threadIdx.x;

    #pragma unroll
    for (int k = 0; k < 2; k++) {
        sW1p[tid + 128 * k] = ((const ulonglong2*)W1)[tid + 128 * k];
        sW2p[tid + 128 * k] = ((const ulonglong2*)W2)[tid + 128 * k];
    }
    if (tid < 16) {
        sW3p[tid] = ((const u64*)W3)[tid];
        sb1p[tid] = ((const u64*)b1)[tid];
        sb2p[tid] = ((const u64*)b2)[tid];
    }
    if (tid == 0) sb3v = b3[0];

    // z features, stored transposed so one LDS.128 yields 4 batches for one i.
    #pragma unroll
    for (int k = 0; k < 2; k++) {
        const int t = tid + 128 * k;
        const int b = t >> 5;
        const int i = t & 31;
        const float zn = 63.0f * z[b];
        const float zt = truncf(zn);
        int z0i = (int)zn;
        if (z0i < 0) z0i = 0;
        if (z0i > 63) z0i = 63;
        int z1i = z0i + 1;
        if (z1i > 63) z1i = 63;
        const float zl = zn - zt;
        szfT[i * 8 + b] = z_data[z0i * 32 + i] * (1.0f - zl) + z_data[z1i * 32 + i] * zl;
    }
    __syncthreads();

    const uint32_t w1base = sptr(sW1p);
    const uint32_t w2base = sptr(sW2p);
    const uint32_t w3base = sptr(sW3p);
    const uint32_t b1base = sptr(sb1p);
    const uint32_t b2base = sptr(sb2p);
    const uint32_t zfbase = sptr(szfT);
    const uint32_t xybase = sptr(sxy) + tid * 33 * 4;

    const int p = blockIdx.x * 128 + tid;

    const float wx = lerp[2 * p + 0];
    const float wy = lerp[2 * p + 1];
    const int ix0 = x0[p], iy0 = y0[p], ix1 = x1[p], iy1 = y1[p];

    const float4* p00 = (const float4*)(data + (iy0 * 512 + ix0) * 32);
    const float4* p10 = (const float4*)(data + (iy0 * 512 + ix1) * 32);
    const float4* p01 = (const float4*)(data + (iy1 * 512 + ix0) * 32);
    const float4* p11 = (const float4*)(data + (iy1 * 512 + ix1) * 32);

    const float w00 = (1.0f - wx) * (1.0f - wy);
    const float w10 = wx * (1.0f - wy);
    const float w01 = (1.0f - wx) * wy;
    const float w11 = wx * wy;

    // Bilinear gather -> per-thread shared (frees 32 registers vs R5).
    #pragma unroll
    for (int q = 0; q < 8; q++) {
        const float4 a = p00[q];
        const float4 c = p10[q];
        const float4 e = p01[q];
        const float4 g = p11[q];
        stsf1v(xybase + (4 * q + 0) * 4, a.x * w00 + c.x * w10 + e.x * w01 + g.x * w11);
        stsf1v(xybase + (4 * q + 1) * 4, a.y * w00 + c.y * w10 + e.y * w01 + g.y * w11);
        stsf1v(xybase + (4 * q + 2) * 4, a.z * w00 + c.z * w10 + e.z * w01 + g.z * w11);
        stsf1v(xybase + (4 * q + 3) * 4, a.w * w00 + c.w * w10 + e.w * w01 + g.w * w11);
    }

    const float bias3 = sb3v;

    // 4 batches per pass: each weight LDS.128 feeds 8 FFMA2.
    #pragma unroll 1
    for (int pass = 0; pass < 2; pass++) {
        // ---- Layer 1: h1[k][jp], k=batch-in-pass, jp=j-pair ----
        u64 h1[64];
        #pragma unroll
        for (int jp = 0; jp < 16; jp++) {
            const u64 bb = lds64v(b1base + 8 * jp);
            h1[0 * 16 + jp] = bb;
            h1[1 * 16 + jp] = bb;
            h1[2 * 16 + jp] = bb;
            h1[3 * 16 + jp] = bb;
        }

        #pragma unroll
        for (int i = 0; i < 32; i++) {
            const float4 zf = ldsf4v(zfbase + i * 32 + pass * 16);
            const float xv = ldsf1v(xybase + i * 4);
            const u64 f0 = dup2(xv * zf.x);
            const u64 f1 = dup2(xv * zf.y);
            const u64 f2 = dup2(xv * zf.z);
            const u64 f3 = dup2(xv * zf.w);
            #pragma unroll
            for (int q = 0; q < 8; q++) {
                const ulonglong2 wv = lds128v(w1base + (i * 8 + q) * 16);
                h1[0 * 16 + 2 * q + 0] = ffma2(f0, wv.x, h1[0 * 16 + 2 * q + 0]);
                h1[0 * 16 + 2 * q + 1] = ffma2(f0, wv.y, h1[0 * 16 + 2 * q + 1]);
                h1[1 * 16 + 2 * q + 0] = ffma2(f1, wv.x, h1[1 * 16 + 2 * q + 0]);
                h1[1 * 16 + 2 * q + 1] = ffma2(f1, wv.y, h1[1 * 16 + 2 * q + 1]);
                h1[2 * 16 + 2 * q + 0] = ffma2(f2, wv.x, h1[2 * 16 + 2 * q + 0]);
                h1[2 * 16 + 2 * q + 1] = ffma2(f2, wv.y, h1[2 * 16 + 2 * q + 1]);
                h1[3 * 16 + 2 * q + 0] = ffma2(f3, wv.x, h1[3 * 16 + 2 * q + 0]);
                h1[3 * 16 + 2 * q + 1] = ffma2(f3, wv.y, h1[3 * 16 + 2 * q + 1]);
            }
        }

        // ---- Layer 2 + Layer 3, fused per j-half (caps h2 at 32 u64) ----
        u64 acc0 = 0ull, acc1 = 0ull, acc2 = 0ull, acc3 = 0ull;  // (0.0f, 0.0f)

        #pragma unroll 1
        for (int half = 0; half < 2; half++) {
            u64 h2[32];   // [k][jp], jp within this half
            #pragma unroll
            for (int jp = 0; jp < 8; jp++) {
                const u64 bb = lds64v(b2base + (8 * half + jp) * 8);
                h2[0 * 8 + jp] = bb;
                h2[1 * 8 + jp] = bb;
                h2[2 * 8 + jp] = bb;
                h2[3 * 8 + jp] = bb;
            }

            #pragma unroll
            for (int ip = 0; ip < 16; ip++) {
                const float2 v0 = unpack2(h1[0 * 16 + ip]);
                const float2 v1 = unpack2(h1[1 * 16 + ip]);
                const float2 v2 = unpack2(h1[2 * 16 + ip]);
                const float2 v3 = unpack2(h1[3 * 16 + ip]);
                {   // activation i = 2*ip
                    const u64 g0 = dup2(fmaxf(v0.x, 0.0f));
                    const u64 g1 = dup2(fmaxf(v1.x, 0.0f));
                    const u64 g2 = dup2(fmaxf(v2.x, 0.0f));
                    const u64 g3 = dup2(fmaxf(v3.x, 0.0f));
                    #pragma unroll
                    for (int q = 0; q < 4; q++) {
                        const ulonglong2 wv = lds128v(w2base + ((2 * ip) * 8 + 4 * half + q) * 16);
                        h2[0 * 8 + 2 * q + 0] = ffma2(g0, wv.x, h2[0 * 8 + 2 * q + 0]);
                        h2[0 * 8 + 2 * q + 1] = ffma2(g0, wv.y, h2[0 * 8 + 2 * q + 1]);
                        h2[1 * 8 + 2 * q + 0] = ffma2(g1, wv.x, h2[1 * 8 + 2 * q + 0]);
                        h2[1 * 8 + 2 * q + 1] = ffma2(g1, wv.y, h2[1 * 8 + 2 * q + 1]);
                        h2[2 * 8 + 2 * q + 0] = ffma2(g2, wv.x, h2[2 * 8 + 2 * q + 0]);
                        h2[2 * 8 + 2 * q + 1] = ffma2(g2, wv.y, h2[2 * 8 + 2 * q + 1]);
                        h2[3 * 8 + 2 * q + 0] = ffma2(g3, wv.x, h2[3 * 8 + 2 * q + 0]);
                        h2[3 * 8 + 2 * q + 1] = ffma2(g3, wv.y, h2[3 * 8 + 2 * q + 1]);
                    }
                }
                {   // activation i = 2*ip + 1
                    const u64 g0 = dup2(fmaxf(v0.y, 0.0f));
                    const u64 g1 = dup2(fmaxf(v1.y, 0.0f));
                    const u64 g2 = dup2(fmaxf(v2.y, 0.0f));
                    const u64 g3 = dup2(fmaxf(v3.y, 0.0f));
                    #pragma unroll
                    for (int q = 0; q < 4; q++) {
                        const ulonglong2 wv = lds128v(w2base + ((2 * ip + 1) * 8 + 4 * half + q) * 16);
                        h2[0 * 8 + 2 * q + 0] = ffma2(g0, wv.x, h2[0 * 8 + 2 * q + 0]);
                        h2[0 * 8 + 2 * q + 1] = ffma2(g0, wv.y, h2[0 * 8 + 2 * q + 1]);
                        h2[1 * 8 + 2 * q + 0] = ffma2(g1, wv.x, h2[1 * 8 + 2 * q + 0]);
                        h2[1 * 8 + 2 * q + 1] = ffma2(g1, wv.y, h2[1 * 8 + 2 * q + 1]);
                        h2[2 * 8 + 2 * q + 0] = ffma2(g2, wv.x, h2[2 * 8 + 2 * q + 0]);
                        h2[2 * 8 + 2 * q + 1] = ffma2(g2, wv.y, h2[2 * 8 + 2 * q + 1]);
                        h2[3 * 8 + 2 * q + 0] = ffma2(g3, wv.x, h2[3 * 8 + 2 * q + 0]);
                        h2[3 * 8 + 2 * q + 1] = ffma2(g3, wv.y, h2[3 * 8 + 2 * q + 1]);
                    }
                }
            }

            // Layer-3 partial dot for this half; frees h2 before next half.
            #pragma unroll
            for (int jp = 0; jp < 8; jp++) {
                const u64 w = lds64v(w3base + (8 * half + jp) * 8);
                const float2 t0 = unpack2(h2[0 * 8 + jp]);
                const float2 t1 = unpack2(h2[1 * 8 + jp]);
                const float2 t2 = unpack2(h2[2 * 8 + jp]);
                const float2 t3 = unpack2(h2[3 * 8 + jp]);
                acc0 = ffma2(pack2(fmaxf(t0.x, 0.0f), fmaxf(t0.y, 0.0f)), w, acc0);
                acc1 = ffma2(pack2(fmaxf(t1.x, 0.0f), fmaxf(t1.y, 0.0f)), w, acc1);
                acc2 = ffma2(pack2(fmaxf(t2.x, 0.0f), fmaxf(t2.y, 0.0f)), w, acc2);
                acc3 = ffma2(pack2(fmaxf(t3.x, 0.0f), fmaxf(t3.y, 0.0f)), w, acc3);
            }
        }

        const float2 r0 = unpack2(acc0);
        const float2 r1 = unpack2(acc1);
        const float2 r2 = unpack2(acc2);
        const float2 r3 = unpack2(acc3);
        out[(4 * pass + 0) * NPIX + p] = r0.x + r0.y + bias3;
        out[(4 * pass + 1) * NPIX + p] = r1.x + r1.y + bias3;
        out[(4 * pass + 2) * NPIX + p] = r2.x + r2.y + bias3;
        out[(4 * pass + 3) * NPIX + p] = r3.x + r3.y + bias3;
    }
}

extern "C" void kernel_launch(void* const* d_in, const int* in_sizes, int n_in,
                              void* d_out, int out_size) {
    const float* z      = (const float*)d_in[0];
    const float* data   = (const float*)d_in[1];
    const float* z_data = (const float*)d_in[2];
    const float* lerp   = (const float*)d_in[3];
    const int*   x0     = (const int*)d_in[4];
    const int*   y0     = (const int*)d_in[5];
    const int*   x1     = (const int*)d_in[6];
    const int*   y1     = (const int*)d_in[7];
    const float* W1     = (const float*)d_in[8];
    const float* b1     = (const float*)d_in[9];
    const float* W2     = (const float*)d_in[10];
    const float* b2     = (const float*)d_in[11];
    const float* W3     = (const float*)d_in[12];
    const float* b3     = (const float*)d_in[13];
    float* out = (float*)d_out;

    g_tensor3d_kernel<<<NPIX / 128, 128>>>(z, data, z_data, lerp,
                                           x0, y0, x1, y1,
                                           W1, b1, W2, b2, W3, b3, out);
}

// round 7
// speedup vs baseline: 23.7328x; 1.0683x over previous
#include <cuda_runtime.h>
#include <cstdint>

#define NPIX (512*512)

typedef unsigned long long u64;

// Packed fp32x2 FMA (Blackwell-only; not emitted by ptxas from C++).
__device__ __forceinline__ u64 ffma2(u64 a, u64 b, u64 c) {
    u64 d;
    asm("fma.rn.f32x2 %0, %1, %2, %3;" : "=l"(d) : "l"(a), "l"(b), "l"(c));
    return d;
}
__device__ __forceinline__ u64 dup2(float f) {
    u64 d;
    unsigned r = __float_as_uint(f);
    asm("mov.b64 %0, {%1, %1};" : "=l"(d) : "r"(r));
    return d;
}
__device__ __forceinline__ u64 pack2(float lo, float hi) {
    u64 d;
    asm("mov.b64 %0, {%1, %2};" : "=l"(d) : "r"(__float_as_uint(lo)), "r"(__float_as_uint(hi)));
    return d;
}
__device__ __forceinline__ float2 unpack2(u64 v) {
    float2 r;
    unsigned lo, hi;
    asm("mov.b64 {%0, %1}, %2;" : "=r"(lo), "=r"(hi) : "l"(v));
    r.x = __uint_as_float(lo); r.y = __uint_as_float(hi);
    return r;
}

// Anti-hoist shared accesses (volatile asm: no CSE / no motion across the
// pass loop -> prevents the giant weight->register promotion that spilled
// in R0/R2/R3).
__device__ __forceinline__ uint32_t sptr(const void* p) {
    return (uint32_t)__cvta_generic_to_shared(p);
}
__device__ __forceinline__ ulonglong2 lds128v(uint32_t addr) {
    ulonglong2 v;
    asm volatile("ld.shared.v2.u64 {%0, %1}, [%2];" : "=l"(v.x), "=l"(v.y) : "r"(addr));
    return v;
}
__device__ __forceinline__ u64 lds64v(uint32_t addr) {
    u64 v;
    asm volatile("ld.shared.u64 %0, [%1];" : "=l"(v) : "r"(addr));
    return v;
}
__device__ __forceinline__ float4 ldsf4v(uint32_t addr) {
    float4 v;
    asm volatile("ld.shared.v4.f32 {%0, %1, %2, %3}, [%4];"
                 : "=f"(v.x), "=f"(v.y), "=f"(v.z), "=f"(v.w) : "r"(addr));
    return v;
}
__device__ __forceinline__ float2 ldsf2v(uint32_t addr) {
    float2 v;
    asm volatile("ld.shared.v2.f32 {%0, %1}, [%2];" : "=f"(v.x), "=f"(v.y) : "r"(addr));
    return v;
}
__device__ __forceinline__ float ldsf1v(uint32_t addr) {
    float v;
    asm volatile("ld.shared.f32 %0, [%1];" : "=f"(v) : "r"(addr));
    return v;
}
__device__ __forceinline__ void stsf1v(uint32_t addr, float v) {
    asm volatile("st.shared.f32 [%0], %1;" :: "r"(addr), "f"(v));
}

__global__ __launch_bounds__(128, 3) void g_tensor3d_kernel(
    const float* __restrict__ z,        // [8]
    const float* __restrict__ data,     // [512,512,32]
    const float* __restrict__ z_data,   // [64,32]
    const float* __restrict__ lerp,     // [NPIX,2]
    const int*   __restrict__ x0,
    const int*   __restrict__ y0,
    const int*   __restrict__ x1,
    const int*   __restrict__ y1,
    const float* __restrict__ W1,       // [32,32]
    const float* __restrict__ b1,
    const float* __restrict__ W2,       // [32,32]
    const float* __restrict__ b2,
    const float* __restrict__ W3,       // [32]
    const float* __restrict__ b3,
    float*       __restrict__ out)      // [8, NPIX]
{
    __shared__ ulonglong2 sW1p[256];    // L1 weights, j-packed: row i = 8 ulonglong2
    __shared__ u64 sW2T[512];           // L2 weights, i-packed: [j][ip] = (W2[2ip][j], W2[2ip+1][j])
    __shared__ u64 sb1p[16];
    __shared__ float2 sb2w3[32];        // (b2[j], W3[j]) interleaved -> one LDS.64 per j
    __shared__ float szfT[256];         // transposed z-features: [i][b]
    __shared__ float sxy[128 * 33];     // per-thread pixel feature, stride 33
    __shared__ float sb3v;

    const int tid = threadIdx.x;

    #pragma unroll
    for (int k = 0; k < 2; k++)
        sW1p[tid + 128 * k] = ((const ulonglong2*)W1)[tid + 128 * k];

    // W2 transposed + i-packed.
    #pragma unroll
    for (int k = 0; k < 4; k++) {
        const int idx = tid + 128 * k;     // 0..511
        const int j  = idx >> 4;
        const int ip = idx & 15;
        sW2T[j * 16 + ip] = pack2(W2[(2 * ip) * 32 + j], W2[(2 * ip + 1) * 32 + j]);
    }
    if (tid < 16) sb1p[tid] = ((const u64*)b1)[tid];
    if (tid < 32) { float2 t; t.x = b2[tid]; t.y = W3[tid]; sb2w3[tid] = t; }
    if (tid == 0) sb3v = b3[0];

    // z features, transposed: one LDS.128 yields 4 batches for one i.
    #pragma unroll
    for (int k = 0; k < 2; k++) {
        const int t = tid + 128 * k;
        const int b = t >> 5;
        const int i = t & 31;
        const float zn = 63.0f * z[b];
        const float zt = truncf(zn);
        int z0i = (int)zn;
        if (z0i < 0) z0i = 0;
        if (z0i > 63) z0i = 63;
        int z1i = z0i + 1;
        if (z1i > 63) z1i = 63;
        const float zl = zn - zt;
        szfT[i * 8 + b] = z_data[z0i * 32 + i] * (1.0f - zl) + z_data[z1i * 32 + i] * zl;
    }
    __syncthreads();

    const uint32_t w1base  = sptr(sW1p);
    const uint32_t w2tbase = sptr(sW2T);
    const uint32_t b1base  = sptr(sb1p);
    const uint32_t bw2base = sptr(sb2w3);
    const uint32_t zfbase  = sptr(szfT);
    const uint32_t xybase  = sptr(sxy) + tid * 33 * 4;

    const int p = blockIdx.x * 128 + tid;

    const float wx = lerp[2 * p + 0];
    const float wy = lerp[2 * p + 1];
    const int ix0 = x0[p], iy0 = y0[p], ix1 = x1[p], iy1 = y1[p];

    const float4* p00 = (const float4*)(data + (iy0 * 512 + ix0) * 32);
    const float4* p10 = (const float4*)(data + (iy0 * 512 + ix1) * 32);
    const float4* p01 = (const float4*)(data + (iy1 * 512 + ix0) * 32);
    const float4* p11 = (const float4*)(data + (iy1 * 512 + ix1) * 32);

    const float w00 = (1.0f - wx) * (1.0f - wy);
    const float w10 = wx * (1.0f - wy);
    const float w01 = (1.0f - wx) * wy;
    const float w11 = wx * wy;

    // Bilinear gather -> per-thread shared lane (keeps registers low).
    #pragma unroll
    for (int q = 0; q < 8; q++) {
        const float4 a = p00[q];
        const float4 c = p10[q];
        const float4 e = p01[q];
        const float4 g = p11[q];
        stsf1v(xybase + (4 * q + 0) * 4, a.x * w00 + c.x * w10 + e.x * w01 + g.x * w11);
        stsf1v(xybase + (4 * q + 1) * 4, a.y * w00 + c.y * w10 + e.y * w01 + g.y * w11);
        stsf1v(xybase + (4 * q + 2) * 4, a.z * w00 + c.z * w10 + e.z * w01 + g.z * w11);
        stsf1v(xybase + (4 * q + 3) * 4, a.w * w00 + c.w * w10 + e.w * w01 + g.w * w11);
    }

    const float bias3 = sb3v;

    // 4 batches per pass; layer-2 streamed per output j so its accumulator
    // footprint is 4 u64 (activations stay in layer-1 packed form).
    #pragma unroll 1
    for (int pass = 0; pass < 2; pass++) {
        // ---- Layer 1: h1[k][jp] packed over j ----
        u64 h1[64];
        #pragma unroll
        for (int jp = 0; jp < 16; jp++) {
            const u64 bb = lds64v(b1base + 8 * jp);
            h1[0 * 16 + jp] = bb;
            h1[1 * 16 + jp] = bb;
            h1[2 * 16 + jp] = bb;
            h1[3 * 16 + jp] = bb;
        }

        #pragma unroll
        for (int i = 0; i < 32; i++) {
            const float4 zf = ldsf4v(zfbase + i * 32 + pass * 16);
            const float xv = ldsf1v(xybase + i * 4);
            const u64 f0 = dup2(xv * zf.x);
            const u64 f1 = dup2(xv * zf.y);
            const u64 f2 = dup2(xv * zf.z);
            const u64 f3 = dup2(xv * zf.w);
            #pragma unroll
            for (int q = 0; q < 8; q++) {
                const ulonglong2 wv = lds128v(w1base + (i * 8 + q) * 16);
                h1[0 * 16 + 2 * q + 0] = ffma2(f0, wv.x, h1[0 * 16 + 2 * q + 0]);
                h1[0 * 16 + 2 * q + 1] = ffma2(f0, wv.y, h1[0 * 16 + 2 * q + 1]);
                h1[1 * 16 + 2 * q + 0] = ffma2(f1, wv.x, h1[1 * 16 + 2 * q + 0]);
                h1[1 * 16 + 2 * q + 1] = ffma2(f1, wv.y, h1[1 * 16 + 2 * q + 1]);
                h1[2 * 16 + 2 * q + 0] = ffma2(f2, wv.x, h1[2 * 16 + 2 * q + 0]);
                h1[2 * 16 + 2 * q + 1] = ffma2(f2, wv.y, h1[2 * 16 + 2 * q + 1]);
                h1[3 * 16 + 2 * q + 0] = ffma2(f3, wv.x, h1[3 * 16 + 2 * q + 0]);
                h1[3 * 16 + 2 * q + 1] = ffma2(f3, wv.y, h1[3 * 16 + 2 * q + 1]);
            }
        }

        // ReLU in place (pairs stay packed over layer-2's i dimension).
        #pragma unroll
        for (int m = 0; m < 64; m++) {
            const float2 v = unpack2(h1[m]);
            h1[m] = pack2(fmaxf(v.x, 0.0f), fmaxf(v.y, 0.0f));
        }

        // ---- Layer 2 + 3 streamed per j: acc_j = h1 . W2T[j], hsum, relu, dot W3 ----
        float o0 = 0.0f, o1 = 0.0f, o2 = 0.0f, o3 = 0.0f;

        #pragma unroll 1
        for (int j = 0; j < 32; j++) {
            u64 a0 = 0ull, a1 = 0ull, a2 = 0ull, a3 = 0ull;
            const uint32_t wb = w2tbase + j * 128;
            #pragma unroll
            for (int q = 0; q < 8; q++) {
                const ulonglong2 wv = lds128v(wb + q * 16);
                a0 = ffma2(h1[0 * 16 + 2 * q + 0], wv.x, a0);
                a1 = ffma2(h1[1 * 16 + 2 * q + 0], wv.x, a1);
                a2 = ffma2(h1[2 * 16 + 2 * q + 0], wv.x, a2);
                a3 = ffma2(h1[3 * 16 + 2 * q + 0], wv.x, a3);
                a0 = ffma2(h1[0 * 16 + 2 * q + 1], wv.y, a0);
                a1 = ffma2(h1[1 * 16 + 2 * q + 1], wv.y, a1);
                a2 = ffma2(h1[2 * 16 + 2 * q + 1], wv.y, a2);
                a3 = ffma2(h1[3 * 16 + 2 * q + 1], wv.y, a3);
            }
            const float2 bw = ldsf2v(bw2base + j * 8);   // (b2[j], W3[j])
            const float2 t0 = unpack2(a0);
            const float2 t1 = unpack2(a1);
            const float2 t2 = unpack2(a2);
            const float2 t3 = unpack2(a3);
            o0 = fmaf(fmaxf(t0.x + t0.y + bw.x, 0.0f), bw.y, o0);
            o1 = fmaf(fmaxf(t1.x + t1.y + bw.x, 0.0f), bw.y, o1);
            o2 = fmaf(fmaxf(t2.x + t2.y + bw.x, 0.0f), bw.y, o2);
            o3 = fmaf(fmaxf(t3.x + t3.y + bw.x, 0.0f), bw.y, o3);
        }

        out[(4 * pass + 0) * NPIX + p] = o0 + bias3;
        out[(4 * pass + 1) * NPIX + p] = o1 + bias3;
        out[(4 * pass + 2) * NPIX + p] = o2 + bias3;
        out[(4 * pass + 3) * NPIX + p] = o3 + bias3;
    }
}

extern "C" void kernel_launch(void* const* d_in, const int* in_sizes, int n_in,
                              void* d_out, int out_size) {
    const float* z      = (const float*)d_in[0];
    const float* data   = (const float*)d_in[1];
    const float* z_data = (const float*)d_in[2];
    const float* lerp   = (const float*)d_in[3];
    const int*   x0     = (const int*)d_in[4];
    const int*   y0     = (const int*)d_in[5];
    const int*   x1     = (const int*)d_in[6];
    const int*   y1     = (const int*)d_in[7];
    const float* W1     = (const float*)d_in[8];
    const float* b1     = (const float*)d_in[9];
    const float* W2     = (const float*)d_in[10];
    const float* b2     = (const float*)d_in[11];
    const float* W3     = (const float*)d_in[12];
    const float* b3     = (const float*)d_in[13];
    float* out = (float*)d_out;

    g_tensor3d_kernel<<<NPIX / 128, 128>>>(z, data, z_data, lerp,
                                           x0, y0, x1, y1,
                                           W1, b1, W2, b2, W3, b3, out);
}